// round 8
// baseline (speedup 1.0000x reference)
#include <cuda_runtime.h>
#include <cstdint>

// Output layout (floats): concatenated mips L0(2048)..L7(16), each [6,H,W,3] row-major.
#define OFF1 75497472ull
#define OFF2 94371840ull
#define OFF3 99090432ull
#define OFF4 100270080ull
#define OFF5 100564992ull
#define OFF6 100638720ull
#define OFF7 100657152ull

// L7 cross-block handoff: each L7 pixel = 2x2 block quadrant group.
// Counters self-reset -> graph-replay safe. Fixed combine order -> deterministic.
__device__ float g_partial[6 * 16 * 16 * 4 * 3];
__device__ int   g_count[6 * 16 * 16];

__device__ __forceinline__ void cp_async16(uint32_t smem_dst, const void* gmem_src) {
    asm volatile("cp.async.cg.shared.global [%0], [%1], 16;" :: "r"(smem_dst), "l"(gmem_src));
}
__device__ __forceinline__ void cp_commit() {
    asm volatile("cp.async.commit_group;" ::: "memory");
}
__device__ __forceinline__ void cp_wait1() {
    asm volatile("cp.async.wait_group 1;" ::: "memory");
}

// Block = 256 threads, tile = 64x64 base px. Grid (32,32,6).
// 4 stages of 16 rows; cp.async double-buffered (depth 2, 12KB/stage).
// Per stage: L0 copy (LDS.128->STG.128); 64 threads each own a 2x2 L1 block
// (4x4 base px) -> L1 + L2 fully in registers (no intermediate smem tile).
// smem ~28KB -> 7 blocks/SM (launch_bounds min-blocks 7).
// Tail L3..L6 block-local; L7 via 4-block quadrant scratch handoff.
__global__ void __launch_bounds__(256, 7) mip_kernel(const float* __restrict__ in,
                                                     float* __restrict__ out) {
    const int t = threadIdx.x;
    const int bx = blockIdx.x, by = blockIdx.y, f = blockIdx.z;

    __shared__ float4 stagebuf[2][768];     // 2 x 12KB: 16 rows x 48 f4
    __shared__ float s2[16][16][3];
    __shared__ float s3[8][8][3];
    __shared__ float s4[4][4][3];
    __shared__ float s5[2][2][3];

    const float4* in4 = reinterpret_cast<const float4*>(in);
    float4* out4 = reinterpret_cast<float4*>(out);

    const uint32_t sb0 = (uint32_t)__cvta_generic_to_shared(&stagebuf[0][0]);
    const uint32_t sb1 = (uint32_t)__cvta_generic_to_shared(&stagebuf[1][0]);

    // f4 offset of stage s row 0; global row stride = 1536 f4.
    auto stage_base = [&](int s) -> size_t {
        return (((size_t)(f * 2048 + by * 64 + s * 16) * 2048 + (size_t)bx * 64) * 3) >> 2;
    };
    auto issue_stage = [&](int s, uint32_t sbase) {
        const size_t gb = stage_base(s);
        #pragma unroll
        for (int k = 0; k < 3; k++) {
            const int idx = k * 256 + t;            // 0..767
            const int r = idx / 48, c = idx % 48;   // 16 rows x 48 f4
            cp_async16(sbase + (uint32_t)idx * 16, in4 + gb + (size_t)r * 1536 + c);
        }
    };

    issue_stage(0, sb0);
    cp_commit();
    issue_stage(1, sb1);
    cp_commit();

    const int xq = t & 15, q = t >> 4;      // compute thread geometry (t < 64)

    #pragma unroll
    for (int s = 0; s < 4; s++) {
        cp_wait1();                          // stage s landed (s+1 in flight)
        __syncthreads();

        const float4* buf = stagebuf[s & 1];
        const float*  buff = reinterpret_cast<const float*>(buf);

        // ---- L0 copy: smem -> global, coalesced ----
        const size_t gb = stage_base(s);
        #pragma unroll
        for (int k = 0; k < 3; k++) {
            const int idx = k * 256 + t;
            const int r = idx / 48, c = idx % 48;
            __stcs(out4 + gb + (size_t)r * 1536 + c, buf[idx]);
        }

        // ---- L1 (2x2 px) + L2 (1 px), registers only; t < 64 ----
        if (t < 64) {
            float acc[3];
            #pragma unroll
            for (int rr = 0; rr < 2; rr++) {
                // base rows 4q+2rr, 4q+2rr+1; px [4*xq, 4*xq+4)
                const float* rA = buff + (4 * q + 2 * rr) * 192 + 12 * xq;
                const float* rB = rA + 192;
                const float4 A0 = reinterpret_cast<const float4*>(rA)[0];
                const float4 A1 = reinterpret_cast<const float4*>(rA)[1];
                const float4 A2 = reinterpret_cast<const float4*>(rA)[2];
                const float4 B0 = reinterpret_cast<const float4*>(rB)[0];
                const float4 B1 = reinterpret_cast<const float4*>(rB)[1];
                const float4 B2 = reinterpret_cast<const float4*>(rB)[2];

                float l1[6];   // [px0.rgb px1.rgb]
                l1[0] = 0.25f * ((A0.x + A0.w) + (B0.x + B0.w));
                l1[1] = 0.25f * ((A0.y + A1.x) + (B0.y + B1.x));
                l1[2] = 0.25f * ((A0.z + A1.y) + (B0.z + B1.y));
                l1[3] = 0.25f * ((A1.z + A2.y) + (B1.z + B2.y));
                l1[4] = 0.25f * ((A1.w + A2.z) + (B1.w + B2.z));
                l1[5] = 0.25f * ((A2.x + A2.w) + (B2.x + B2.w));

                const int y1 = by * 32 + s * 8 + 2 * q + rr;
                const size_t o1 = OFF1 +
                    ((size_t)(f * 1024 + y1) * 1024 + (size_t)(bx * 32 + 2 * xq)) * 3;
                float2* q1 = reinterpret_cast<float2*>(out + o1);   // 8B aligned
                __stcs(q1 + 0, make_float2(l1[0], l1[1]));
                __stcs(q1 + 1, make_float2(l1[2], l1[3]));
                __stcs(q1 + 2, make_float2(l1[4], l1[5]));

                #pragma unroll
                for (int c = 0; c < 3; c++) {
                    const float h = l1[c] + l1[3 + c];
                    if (rr == 0) acc[c] = h; else acc[c] = acc[c] + h;
                }
            }
            const int y2 = by * 16 + s * 4 + q;
            const size_t o2 = OFF2 +
                ((size_t)(f * 512 + y2) * 512 + (size_t)(bx * 16 + xq)) * 3;
            #pragma unroll
            for (int c = 0; c < 3; c++) {
                const float w = 0.25f * acc[c];
                __stcs(out + o2 + c, w);
                s2[s * 4 + q][xq][c] = w;
            }
        }
        __syncthreads();                     // stagebuf[s&1] fully consumed

        if (s + 2 < 4)
            issue_stage(s + 2, (s & 1) ? sb1 : sb0);
        cp_commit();
    }
    __syncthreads();                          // s2 complete (16x16)

    // ---- L3: 8x8 per block (face 256) ----
    if (t < 64) {
        const int x = t & 7, y = t >> 3;
        const size_t o = OFF3 + ((size_t)(f * 256 + by * 8 + y) * 256 + (size_t)(bx * 8 + x)) * 3;
        #pragma unroll
        for (int c = 0; c < 3; c++) {
            const float w = 0.25f * (s2[2 * y][2 * x][c] + s2[2 * y][2 * x + 1][c] +
                                     s2[2 * y + 1][2 * x][c] + s2[2 * y + 1][2 * x + 1][c]);
            __stcs(out + o + c, w);
            s3[y][x][c] = w;
        }
    }
    __syncthreads();

    // ---- L4: 4x4 per block (face 128) ----
    if (t < 16) {
        const int x = t & 3, y = t >> 2;
        const size_t o = OFF4 + ((size_t)(f * 128 + by * 4 + y) * 128 + (size_t)(bx * 4 + x)) * 3;
        #pragma unroll
        for (int c = 0; c < 3; c++) {
            const float w = 0.25f * (s3[2 * y][2 * x][c] + s3[2 * y][2 * x + 1][c] +
                                     s3[2 * y + 1][2 * x][c] + s3[2 * y + 1][2 * x + 1][c]);
            __stcs(out + o + c, w);
            s4[y][x][c] = w;
        }
    }
    __syncthreads();

    // ---- L5: 2x2 per block (face 64) ----
    if (t < 4) {
        const int x = t & 1, y = t >> 1;
        const size_t o = OFF5 + ((size_t)(f * 64 + by * 2 + y) * 64 + (size_t)(bx * 2 + x)) * 3;
        #pragma unroll
        for (int c = 0; c < 3; c++) {
            const float w = 0.25f * (s4[2 * y][2 * x][c] + s4[2 * y][2 * x + 1][c] +
                                     s4[2 * y + 1][2 * x][c] + s4[2 * y + 1][2 * x + 1][c]);
            __stcs(out + o + c, w);
            s5[y][x][c] = w;
        }
    }
    __syncthreads();

    // ---- L6: 1 px per block (face 32) + L7 quadrant handoff (face 16) ----
    if (t == 0) {
        float v6[3];
        const size_t o6 = OFF6 + ((size_t)(f * 32 + by) * 32 + bx) * 3;
        #pragma unroll
        for (int c = 0; c < 3; c++) {
            v6[c] = 0.25f * (s5[0][0][c] + s5[0][1][c] + s5[1][0][c] + s5[1][1][c]);
            __stcs(out + o6 + c, v6[c]);
        }

        const int X7 = bx >> 1, Y7 = by >> 1;
        const int qd = (by & 1) * 2 + (bx & 1);
        const int idx = (f * 16 + Y7) * 16 + X7;
        float* slot = g_partial + ((size_t)idx * 4 + qd) * 3;
        slot[0] = v6[0]; slot[1] = v6[1]; slot[2] = v6[2];
        __threadfence();
        const int old = atomicAdd(&g_count[idx], 1);
        if (old == 3) {                       // last arriver combines
            __threadfence();
            const float* sp = g_partial + (size_t)idx * 4 * 3;
            const size_t o7 = OFF7 + ((size_t)(f * 16 + Y7) * 16 + X7) * 3;
            #pragma unroll
            for (int c = 0; c < 3; c++)
                out[o7 + c] = 0.25f * ((sp[c] + sp[3 + c]) + (sp[6 + c] + sp[9 + c]));
            atomicExch(&g_count[idx], 0);     // reset for next graph replay
        }
    }
}

extern "C" void kernel_launch(void* const* d_in, const int* in_sizes, int n_in,
                              void* d_out, int out_size) {
    const float* base = (const float*)d_in[0];
    float* out = (float*)d_out;
    mip_kernel<<<dim3(32, 32, 6), 256>>>(base, out);
}